// round 1
// baseline (speedup 1.0000x reference)
#include <cuda_runtime.h>

#define NN 50000
#define EE 800000
#define INCH 128
#define C1 64
#define C2 32
#define SLOPE 0.2f

// -------- device scratch (allocation-free: __device__ globals) --------
__device__ __align__(256) float g_h1[NN * C1];     // layer1 projected features
__device__ __align__(256) float g_agg1[NN * C1];   // layer1 unnormalized aggregate
__device__ __align__(256) float g_h2[NN * C2];     // layer2 projected features
__device__ __align__(256) float g_agg2[NN * C2];   // layer2 unnormalized aggregate
__device__ float g_ls[NN];        // per-node src score (reused per layer)
__device__ float g_ld[NN];        // per-node dst score (reused per layer)
__device__ unsigned g_m[NN];      // ordered-uint segment max (reused per layer)
__device__ float g_den[NN];       // segment softmax denominator (reused per layer)
__device__ float g_logit[EE];     // per-edge leaky-relu logit

// monotonic float<->uint mapping for atomicMax on floats
__device__ __forceinline__ unsigned fmap(float f) {
    unsigned u = __float_as_uint(f);
    return (u & 0x80000000u) ? ~u : (u | 0x80000000u);
}
__device__ __forceinline__ float funmap(unsigned u) {
    unsigned v = (u & 0x80000000u) ? (u & 0x7fffffffu) : ~u;
    return __uint_as_float(v);
}

// -------- zero fill --------
__global__ void zero_f(float* __restrict__ p, int n) {
    int i = blockIdx.x * blockDim.x + threadIdx.x;
    if (i < n) p[i] = 0.f;
}

// -------- layer1 projection: h1 = x @ W1, ls = h1@a_src, ld = h1@a_dst --------
__global__ __launch_bounds__(256) void gemm1_kernel(
    const float* __restrict__ x, const float* __restrict__ W,
    const float* __restrict__ asrc, const float* __restrict__ adst)
{
    __shared__ float Ws[INCH * C1];   // 32 KB
    __shared__ float xs[4 * INCH];    // 2 KB
    __shared__ float reds[8], redd[8];
    int tid = threadIdx.x;
    for (int i = tid; i < INCH * C1; i += 256) Ws[i] = W[i];
    int sub = tid >> 6, c = tid & 63;
    float as = asrc[c], ad = adst[c];

    for (int base = blockIdx.x * 4; base < NN; base += gridDim.x * 4) {
        __syncthreads();
        #pragma unroll
        for (int it = 0; it < 2; it++) {
            int idx = it * 256 + tid;
            int nl = base + (idx >> 7);
            xs[idx] = (nl < NN) ? x[(size_t)nl * INCH + (idx & 127)] : 0.f;
        }
        __syncthreads();
        int node = base + sub;
        float acc = 0.f;
        const float* xr = &xs[sub * INCH];
        #pragma unroll 8
        for (int k = 0; k < INCH; k++) acc = fmaf(xr[k], Ws[k * C1 + c], acc);

        // reduce ls/ld over the 64 channels of this node (2 warps per node)
        float ps = acc * as, pd = acc * ad;
        #pragma unroll
        for (int off = 16; off > 0; off >>= 1) {
            ps += __shfl_down_sync(0xffffffffu, ps, off);
            pd += __shfl_down_sync(0xffffffffu, pd, off);
        }
        int wid = tid >> 5;
        if ((tid & 31) == 0) { reds[wid] = ps; redd[wid] = pd; }
        __syncthreads();
        if (node < NN) {
            g_h1[(size_t)node * C1 + c] = acc;
            if (c == 0) {
                g_ls[node] = reds[2 * sub] + reds[2 * sub + 1];
                g_ld[node] = redd[2 * sub] + redd[2 * sub + 1];
            }
        }
    }
}

// -------- layer2 projection (fused layer1 epilogue: /den + b1 + relu) --------
__global__ __launch_bounds__(256) void gemm2_kernel(
    const float* __restrict__ b1, const float* __restrict__ W,
    const float* __restrict__ asrc, const float* __restrict__ adst)
{
    __shared__ float Ws[C1 * C2];  // 8 KB
    __shared__ float xs[8 * C1];   // 2 KB
    int tid = threadIdx.x;
    for (int i = tid; i < C1 * C2; i += 256) Ws[i] = W[i];
    int sub = tid >> 5, c = tid & 31;
    float as = asrc[c], ad = adst[c];

    for (int base = blockIdx.x * 8; base < NN; base += gridDim.x * 8) {
        __syncthreads();
        #pragma unroll
        for (int it = 0; it < 2; it++) {
            int idx = it * 256 + tid;
            int nl = base + (idx >> 6);
            int k = idx & 63;
            float v = 0.f;
            if (nl < NN) {
                float den = g_den[nl];
                float inv = den > 0.f ? 1.f / den : 0.f;
                v = g_agg1[(size_t)nl * C1 + k] * inv + b1[k];
                v = v > 0.f ? v : 0.f;   // relu
            }
            xs[idx] = v;
        }
        __syncthreads();
        int node = base + sub;
        float acc = 0.f;
        const float* xr = &xs[sub * C1];
        #pragma unroll 8
        for (int k = 0; k < C1; k++) acc = fmaf(xr[k], Ws[k * C2 + c], acc);

        float ps = acc * as, pd = acc * ad;
        #pragma unroll
        for (int off = 16; off > 0; off >>= 1) {
            ps += __shfl_down_sync(0xffffffffu, ps, off);
            pd += __shfl_down_sync(0xffffffffu, pd, off);
        }
        if (node < NN) {
            g_h2[(size_t)node * C2 + c] = acc;
            if (c == 0) { g_ls[node] = ps; g_ld[node] = pd; }
        }
    }
}

// -------- edge pass A: logits + segment max --------
__global__ void edge_logits(const int* __restrict__ src, const int* __restrict__ dst)
{
    int e = blockIdx.x * blockDim.x + threadIdx.x;
    if (e >= EE) return;
    int d = dst[e];
    float l = g_ls[src[e]] + g_ld[d];
    l = l > 0.f ? l : SLOPE * l;     // leaky relu
    g_logit[e] = l;
    atomicMax(&g_m[d], fmap(l));
}

// -------- edge pass B: exp, denom, unnormalized aggregate (vector red) --------
template <int C>
__global__ void edge_aggregate(const int* __restrict__ src, const int* __restrict__ dst,
                               const float* __restrict__ h, float* __restrict__ agg)
{
    const int TPE = C / 4;  // threads per edge, one float4 each
    int gi = blockIdx.x * blockDim.x + threadIdx.x;
    int e = gi / TPE;
    int lane = gi % TPE;
    if (e >= EE) return;
    int s = src[e], d = dst[e];
    float m = funmap(g_m[d]);
    float ev = __expf(g_logit[e] - m);
    if (lane == 0) atomicAdd(&g_den[d], ev);
    float4 hv = *reinterpret_cast<const float4*>(h + (size_t)s * C + lane * 4);
    float4 r = make_float4(hv.x * ev, hv.y * ev, hv.z * ev, hv.w * ev);
    float* p = agg + (size_t)d * C + lane * 4;
    asm volatile("red.global.add.v4.f32 [%0], {%1,%2,%3,%4};"
                 :: "l"(p), "f"(r.x), "f"(r.y), "f"(r.z), "f"(r.w) : "memory");
}

// -------- final epilogue: out = agg2/den + b2 --------
__global__ void finalize_kernel(const float* __restrict__ b2, float* __restrict__ out)
{
    int i = blockIdx.x * blockDim.x + threadIdx.x;
    if (i >= NN * C2) return;
    int n = i >> 5, c = i & 31;
    float den = g_den[n];
    float inv = den > 0.f ? 1.f / den : 0.f;
    out[i] = g_agg2[i] * inv + b2[c];
}

extern "C" void kernel_launch(void* const* d_in, const int* in_sizes, int n_in,
                              void* d_out, int out_size)
{
    const float* x   = (const float*)d_in[0];
    const int*   ei  = (const int*)d_in[1];
    const float* W1  = (const float*)d_in[2];
    const float* as1 = (const float*)d_in[3];
    const float* ad1 = (const float*)d_in[4];
    const float* b1  = (const float*)d_in[5];
    const float* W2  = (const float*)d_in[6];
    const float* as2 = (const float*)d_in[7];
    const float* ad2 = (const float*)d_in[8];
    const float* b2  = (const float*)d_in[9];
    const int* src = ei;
    const int* dst = ei + EE;

    float *p_agg1, *p_agg2, *p_den, *p_h1, *p_h2;
    unsigned* p_m;
    cudaGetSymbolAddress((void**)&p_agg1, g_agg1);
    cudaGetSymbolAddress((void**)&p_agg2, g_agg2);
    cudaGetSymbolAddress((void**)&p_den,  g_den);
    cudaGetSymbolAddress((void**)&p_h1,   g_h1);
    cudaGetSymbolAddress((void**)&p_h2,   g_h2);
    cudaGetSymbolAddress((void**)&p_m,    g_m);

    const int T = 256;

    // ---- layer 1 ----
    zero_f<<<(NN * C1 + T - 1) / T, T>>>(p_agg1, NN * C1);
    zero_f<<<(NN + T - 1) / T, T>>>(p_den, NN);
    zero_f<<<(NN + T - 1) / T, T>>>((float*)p_m, NN);
    gemm1_kernel<<<592, T>>>(x, W1, as1, ad1);
    edge_logits<<<(EE + T - 1) / T, T>>>(src, dst);
    edge_aggregate<C1><<<(EE * (C1 / 4) + T - 1) / T, T>>>(src, dst, p_h1, p_agg1);

    // ---- layer 2 (gemm2 consumes layer1 den/agg BEFORE re-zeroing) ----
    gemm2_kernel<<<592, T>>>(b1, W2, as2, ad2);
    zero_f<<<(NN * C2 + T - 1) / T, T>>>(p_agg2, NN * C2);
    zero_f<<<(NN + T - 1) / T, T>>>(p_den, NN);
    zero_f<<<(NN + T - 1) / T, T>>>((float*)p_m, NN);
    edge_logits<<<(EE + T - 1) / T, T>>>(src, dst);
    edge_aggregate<C2><<<(EE * (C2 / 4) + T - 1) / T, T>>>(src, dst, p_h2, p_agg2);

    finalize_kernel<<<(NN * C2 + T - 1) / T, T>>>(b2, (float*)d_out);
}

// round 2
// speedup vs baseline: 1.5413x; 1.5413x over previous
#include <cuda_runtime.h>

#define NN 50000
#define EE 800000
#define INCH 128
#define C1 64
#define C2 32
#define SLOPE 0.2f

// -------- device scratch (allocation-free: __device__ globals) --------
__device__ __align__(256) float g_h1[NN * C1];
__device__ __align__(256) float g_agg1[NN * C1];
__device__ __align__(256) float g_h2[NN * C2];
__device__ __align__(256) float g_agg2[NN * C2];
__device__ float g_ls[NN];
__device__ float g_ld[NN];
__device__ float g_den[NN];

// -------- zero fill (two buffers in one launch) --------
__global__ void zero2_f(float* __restrict__ p1, int n1, float* __restrict__ p2, int n2) {
    int i = blockIdx.x * blockDim.x + threadIdx.x;
    if (i < n1) p1[i] = 0.f;
    if (i < n2) p2[i] = 0.f;
}

// ============================================================
// Layer1 projection, register tiled: 64 nodes/block, 256 threads,
// each thread computes a 4-node x 4-channel tile.
// Dynamic smem: Ws[128*64] (32KB) + xs[64*132] (33KB) = 66560B.
// ============================================================
#define G1_XSTRIDE 132
__global__ __launch_bounds__(256) void gemm1_kernel(
    const float* __restrict__ x, const float* __restrict__ W,
    const float* __restrict__ asrc, const float* __restrict__ adst)
{
    extern __shared__ float sm[];
    float* Ws = sm;               // 8192 floats
    float* xs = sm + INCH * C1;   // 64*132 = 8448 floats

    int tid = threadIdx.x;
    int tx = tid & 15;            // c-group: channels tx*4 .. tx*4+3
    int ty = tid >> 4;            // node-group: nodes ty*4 .. ty*4+3
    int base = blockIdx.x * 64;

    // stage W (coalesced, as float4)
    const float4* W4 = (const float4*)W;
    float4* Ws4v = (float4*)Ws;
    #pragma unroll
    for (int i = tid; i < INCH * C1 / 4; i += 256) Ws4v[i] = W4[i];

    // stage x tile: 64 nodes x 128 ch = 2048 float4
    const float4* x4 = (const float4*)x;
    #pragma unroll
    for (int it = 0; it < 8; it++) {
        int f = it * 256 + tid;               // float4 index
        int n = f >> 5;                       // 32 float4 per row
        int k4 = f & 31;
        float4 v = make_float4(0.f, 0.f, 0.f, 0.f);
        if (base + n < NN) v = x4[(size_t)(base + n) * 32 + k4];
        *(float4*)&xs[n * G1_XSTRIDE + k4 * 4] = v;
    }
    __syncthreads();

    float acc[4][4];
    #pragma unroll
    for (int i = 0; i < 4; i++)
        #pragma unroll
        for (int j = 0; j < 4; j++) acc[i][j] = 0.f;

    const float4* WsRow = (const float4*)Ws + tx;     // row k: WsRow[k*16]
    const float* xr0 = &xs[(ty * 4 + 0) * G1_XSTRIDE];
    const float* xr1 = &xs[(ty * 4 + 1) * G1_XSTRIDE];
    const float* xr2 = &xs[(ty * 4 + 2) * G1_XSTRIDE];
    const float* xr3 = &xs[(ty * 4 + 3) * G1_XSTRIDE];

    #pragma unroll 4
    for (int k = 0; k < INCH; k++) {
        float4 w = WsRow[k * 16];
        float x0 = xr0[k], x1 = xr1[k], x2 = xr2[k], x3 = xr3[k];
        acc[0][0] = fmaf(x0, w.x, acc[0][0]); acc[0][1] = fmaf(x0, w.y, acc[0][1]);
        acc[0][2] = fmaf(x0, w.z, acc[0][2]); acc[0][3] = fmaf(x0, w.w, acc[0][3]);
        acc[1][0] = fmaf(x1, w.x, acc[1][0]); acc[1][1] = fmaf(x1, w.y, acc[1][1]);
        acc[1][2] = fmaf(x1, w.z, acc[1][2]); acc[1][3] = fmaf(x1, w.w, acc[1][3]);
        acc[2][0] = fmaf(x2, w.x, acc[2][0]); acc[2][1] = fmaf(x2, w.y, acc[2][1]);
        acc[2][2] = fmaf(x2, w.z, acc[2][2]); acc[2][3] = fmaf(x2, w.w, acc[2][3]);
        acc[3][0] = fmaf(x3, w.x, acc[3][0]); acc[3][1] = fmaf(x3, w.y, acc[3][1]);
        acc[3][2] = fmaf(x3, w.z, acc[3][2]); acc[3][3] = fmaf(x3, w.w, acc[3][3]);
    }

    // store h1 (float4 per node)
    #pragma unroll
    for (int i = 0; i < 4; i++) {
        int node = base + ty * 4 + i;
        if (node < NN)
            *(float4*)&g_h1[(size_t)node * C1 + tx * 4] =
                make_float4(acc[i][0], acc[i][1], acc[i][2], acc[i][3]);
    }

    // ls/ld reduction: partial per (node, c-group) into reused xs space
    float as0 = asrc[tx * 4 + 0], as1 = asrc[tx * 4 + 1], as2 = asrc[tx * 4 + 2], as3 = asrc[tx * 4 + 3];
    float ad0 = adst[tx * 4 + 0], ad1 = adst[tx * 4 + 1], ad2 = adst[tx * 4 + 2], ad3 = adst[tx * 4 + 3];
    __syncthreads();
    float* redS = xs;             // 64*17
    float* redD = xs + 64 * 17;   // 64*17
    #pragma unroll
    for (int i = 0; i < 4; i++) {
        int nl = ty * 4 + i;
        float ps = acc[i][0] * as0 + acc[i][1] * as1 + acc[i][2] * as2 + acc[i][3] * as3;
        float pd = acc[i][0] * ad0 + acc[i][1] * ad1 + acc[i][2] * ad2 + acc[i][3] * ad3;
        redS[nl * 17 + tx] = ps;
        redD[nl * 17 + tx] = pd;
    }
    __syncthreads();
    if (tid < 64) {
        int node = base + tid;
        if (node < NN) {
            float s = 0.f, d = 0.f;
            #pragma unroll
            for (int t = 0; t < 16; t++) { s += redS[tid * 17 + t]; d += redD[tid * 17 + t]; }
            g_ls[node] = s;
            g_ld[node] = d;
        }
    }
}

// ============================================================
// Layer2 projection with fused layer1 epilogue (/den + b1 + relu).
// 128 nodes/block, 256 threads, thread = 4 nodes x 4 channels.
// Static smem: Ws 8KB + xs 128*69*4 = 34.5KB.
// ============================================================
#define G2_XSTRIDE 69
__global__ __launch_bounds__(256) void gemm2_kernel(
    const float* __restrict__ b1, const float* __restrict__ W,
    const float* __restrict__ asrc, const float* __restrict__ adst)
{
    __shared__ float Ws[C1 * C2];
    __shared__ float xs[128 * G2_XSTRIDE];

    int tid = threadIdx.x;
    int tx = tid & 7;             // c-group: channels tx*4..+3  (8 groups x 4 = 32)
    int ty = tid >> 3;            // node-group: nodes ty*4..+3  (32 groups x 4 = 128)
    int base = blockIdx.x * 128;

    for (int i = tid; i < C1 * C2; i += 256) Ws[i] = W[i];

    // stage x tile with epilogue: 128 nodes x 64 ch
    #pragma unroll
    for (int it = 0; it < 32; it++) {
        int idx = it * 256 + tid;
        int n = idx >> 6, k = idx & 63;
        int node = base + n;
        float v = 0.f;
        if (node < NN) {
            float den = g_den[node];
            float inv = den > 0.f ? 1.f / den : 0.f;
            v = g_agg1[(size_t)node * C1 + k] * inv + b1[k];
            v = v > 0.f ? v : 0.f;
        }
        xs[n * G2_XSTRIDE + k] = v;
    }
    __syncthreads();

    float acc[4][4];
    #pragma unroll
    for (int i = 0; i < 4; i++)
        #pragma unroll
        for (int j = 0; j < 4; j++) acc[i][j] = 0.f;

    const float4* WsRow = (const float4*)Ws + tx;     // row k: WsRow[k*8]
    const float* xr0 = &xs[(ty * 4 + 0) * G2_XSTRIDE];
    const float* xr1 = &xs[(ty * 4 + 1) * G2_XSTRIDE];
    const float* xr2 = &xs[(ty * 4 + 2) * G2_XSTRIDE];
    const float* xr3 = &xs[(ty * 4 + 3) * G2_XSTRIDE];

    #pragma unroll 4
    for (int k = 0; k < C1; k++) {
        float4 w = WsRow[k * 8];
        float x0 = xr0[k], x1 = xr1[k], x2 = xr2[k], x3 = xr3[k];
        acc[0][0] = fmaf(x0, w.x, acc[0][0]); acc[0][1] = fmaf(x0, w.y, acc[0][1]);
        acc[0][2] = fmaf(x0, w.z, acc[0][2]); acc[0][3] = fmaf(x0, w.w, acc[0][3]);
        acc[1][0] = fmaf(x1, w.x, acc[1][0]); acc[1][1] = fmaf(x1, w.y, acc[1][1]);
        acc[1][2] = fmaf(x1, w.z, acc[1][2]); acc[1][3] = fmaf(x1, w.w, acc[1][3]);
        acc[2][0] = fmaf(x2, w.x, acc[2][0]); acc[2][1] = fmaf(x2, w.y, acc[2][1]);
        acc[2][2] = fmaf(x2, w.z, acc[2][2]); acc[2][3] = fmaf(x2, w.w, acc[2][3]);
        acc[3][0] = fmaf(x3, w.x, acc[3][0]); acc[3][1] = fmaf(x3, w.y, acc[3][1]);
        acc[3][2] = fmaf(x3, w.z, acc[3][2]); acc[3][3] = fmaf(x3, w.w, acc[3][3]);
    }

    #pragma unroll
    for (int i = 0; i < 4; i++) {
        int node = base + ty * 4 + i;
        if (node < NN)
            *(float4*)&g_h2[(size_t)node * C2 + tx * 4] =
                make_float4(acc[i][0], acc[i][1], acc[i][2], acc[i][3]);
    }

    float as0 = asrc[tx * 4 + 0], as1 = asrc[tx * 4 + 1], as2 = asrc[tx * 4 + 2], as3 = asrc[tx * 4 + 3];
    float ad0 = adst[tx * 4 + 0], ad1 = adst[tx * 4 + 1], ad2 = adst[tx * 4 + 2], ad3 = adst[tx * 4 + 3];
    __syncthreads();
    float* redS = xs;              // 128*9
    float* redD = xs + 128 * 9;    // 128*9
    #pragma unroll
    for (int i = 0; i < 4; i++) {
        int nl = ty * 4 + i;
        float ps = acc[i][0] * as0 + acc[i][1] * as1 + acc[i][2] * as2 + acc[i][3] * as3;
        float pd = acc[i][0] * ad0 + acc[i][1] * ad1 + acc[i][2] * ad2 + acc[i][3] * ad3;
        redS[nl * 9 + tx] = ps;
        redD[nl * 9 + tx] = pd;
    }
    __syncthreads();
    if (tid < 128) {
        int node = base + tid;
        if (node < NN) {
            float s = 0.f, d = 0.f;
            #pragma unroll
            for (int t = 0; t < 8; t++) { s += redS[tid * 9 + t]; d += redD[tid * 9 + t]; }
            g_ls[node] = s;
            g_ld[node] = d;
        }
    }
}

// ============================================================
// Fused edge pass: logit -> exp (no max shift; softmax is
// shift-invariant and logits are O(1) here) -> denom atomic ->
// unnormalized vector-red aggregate. One pass per layer.
// ============================================================
template <int C>
__global__ void edge_fused(const int* __restrict__ src, const int* __restrict__ dst,
                           const float* __restrict__ h, float* __restrict__ agg)
{
    const int TPE = C / 4;  // threads per edge, one float4 each
    int gi = blockIdx.x * blockDim.x + threadIdx.x;
    int e = gi / TPE;
    int lane = gi % TPE;
    if (e >= EE) return;
    int s = src[e], d = dst[e];
    float ev = 0.f;
    if (lane == 0) {
        float l = g_ls[s] + g_ld[d];
        l = l > 0.f ? l : SLOPE * l;
        ev = __expf(l);
        atomicAdd(&g_den[d], ev);
    }
    int leader = (threadIdx.x & 31) & ~(TPE - 1);
    ev = __shfl_sync(0xffffffffu, ev, leader);
    float4 hv = *reinterpret_cast<const float4*>(h + (size_t)s * C + lane * 4);
    float* p = agg + (size_t)d * C + lane * 4;
    asm volatile("red.global.add.v4.f32 [%0], {%1,%2,%3,%4};"
                 :: "l"(p), "f"(hv.x * ev), "f"(hv.y * ev), "f"(hv.z * ev), "f"(hv.w * ev)
                 : "memory");
}

// -------- final epilogue: out = agg2/den + b2 --------
__global__ void finalize_kernel(const float* __restrict__ b2, float* __restrict__ out)
{
    int i = blockIdx.x * blockDim.x + threadIdx.x;
    if (i >= NN * C2) return;
    int n = i >> 5, c = i & 31;
    float den = g_den[n];
    float inv = den > 0.f ? 1.f / den : 0.f;
    out[i] = g_agg2[i] * inv + b2[c];
}

extern "C" void kernel_launch(void* const* d_in, const int* in_sizes, int n_in,
                              void* d_out, int out_size)
{
    const float* x   = (const float*)d_in[0];
    const int*   ei  = (const int*)d_in[1];
    const float* W1  = (const float*)d_in[2];
    const float* as1 = (const float*)d_in[3];
    const float* ad1 = (const float*)d_in[4];
    const float* b1  = (const float*)d_in[5];
    const float* W2  = (const float*)d_in[6];
    const float* as2 = (const float*)d_in[7];
    const float* ad2 = (const float*)d_in[8];
    const float* b2  = (const float*)d_in[9];
    const int* src = ei;
    const int* dst = ei + EE;

    float *p_agg1, *p_agg2, *p_den, *p_h1, *p_h2;
    cudaGetSymbolAddress((void**)&p_agg1, g_agg1);
    cudaGetSymbolAddress((void**)&p_agg2, g_agg2);
    cudaGetSymbolAddress((void**)&p_den,  g_den);
    cudaGetSymbolAddress((void**)&p_h1,   g_h1);
    cudaGetSymbolAddress((void**)&p_h2,   g_h2);

    static bool attr_set = false;
    if (!attr_set) {
        cudaFuncSetAttribute(gemm1_kernel, cudaFuncAttributeMaxDynamicSharedMemorySize,
                             (INCH * C1 + 64 * G1_XSTRIDE) * 4);
        attr_set = true;
    }

    const int T = 256;

    // ---- layer 1 ----
    zero2_f<<<(NN * C1 + T - 1) / T, T>>>(p_agg1, NN * C1, p_den, NN);
    gemm1_kernel<<<(NN + 63) / 64, T, (INCH * C1 + 64 * G1_XSTRIDE) * 4>>>(x, W1, as1, ad1);
    edge_fused<C1><<<EE * (C1 / 4) / T, T>>>(src, dst, p_h1, p_agg1);

    // ---- layer 2 (gemm2 consumes layer1 den/agg BEFORE re-zeroing den) ----
    gemm2_kernel<<<(NN + 127) / 128, T>>>(b1, W2, as2, ad2);
    zero2_f<<<(NN * C2 + T - 1) / T, T>>>(p_agg2, NN * C2, p_den, NN);
    edge_fused<C2><<<EE * (C2 / 4) / T, T>>>(src, dst, p_h2, p_agg2);

    finalize_kernel<<<(NN * C2 + T - 1) / T, T>>>(b2, (float*)d_out);
}

// round 3
// speedup vs baseline: 1.7667x; 1.1463x over previous
#include <cuda_runtime.h>

#define NN 50000
#define EE 800000
#define INCH 128
#define C1 64
#define C2 32
#define SLOPE 0.2f

// -------- device scratch --------
__device__ __align__(256) float g_h1[NN * C1];
__device__ __align__(256) float g_agg1[NN * C1];
__device__ __align__(256) float g_h2[NN * C2];
__device__ __align__(256) float g_agg2[NN * C2];
__device__ float g_ls[NN];
__device__ float g_ld[NN];
__device__ float g_den[NN];

// ============================================================
// Layer1 projection + fused zero of agg1/den.
// 128 nodes/block, 512 threads, thread = 4 nodes x 4 channels.
// Dynamic smem: Ws[128*64] (32KB) + xs[128*132] (67.6KB) = 99.6KB -> 2 blocks/SM.
// ============================================================
#define G1_XSTRIDE 132
#define G1_SMEM ((INCH * C1 + 128 * G1_XSTRIDE) * 4)
__global__ __launch_bounds__(512) void gemm1_kernel(
    const float* __restrict__ x, const float* __restrict__ W,
    const float* __restrict__ asrc, const float* __restrict__ adst)
{
    extern __shared__ float sm[];
    float* Ws = sm;               // 8192 floats
    float* xs = sm + INCH * C1;   // 128*132 floats

    int tid = threadIdx.x;
    int tx = tid & 15;            // channels tx*4 .. tx*4+3
    int ty = tid >> 4;            // nodes ty*4 .. ty*4+3 (32 groups)
    int base = blockIdx.x * 128;

    // fused zeroing: agg1 rows for this block's nodes + den
    {
        float4 z4 = make_float4(0.f, 0.f, 0.f, 0.f);
        #pragma unroll
        for (int it = 0; it < 4; it++) {
            int f = it * 512 + tid;           // 2048 float4 = 128 nodes * 16
            int n = base + (f >> 4);
            if (n < NN) *(float4*)&g_agg1[(size_t)n * C1 + (f & 15) * 4] = z4;
        }
        if (tid < 128 && base + tid < NN) g_den[base + tid] = 0.f;
    }

    // stage W
    const float4* W4 = (const float4*)W;
    float4* Ws4v = (float4*)Ws;
    #pragma unroll
    for (int i = tid; i < INCH * C1 / 4; i += 512) Ws4v[i] = W4[i];

    // stage x tile: 128 nodes x 32 float4
    const float4* x4 = (const float4*)x;
    #pragma unroll
    for (int it = 0; it < 8; it++) {
        int f = it * 512 + tid;
        int n = f >> 5;
        int k4 = f & 31;
        float4 v = make_float4(0.f, 0.f, 0.f, 0.f);
        if (base + n < NN) v = x4[(size_t)(base + n) * 32 + k4];
        *(float4*)&xs[n * G1_XSTRIDE + k4 * 4] = v;
    }
    __syncthreads();

    float acc[4][4];
    #pragma unroll
    for (int i = 0; i < 4; i++)
        #pragma unroll
        for (int j = 0; j < 4; j++) acc[i][j] = 0.f;

    const float4* WsRow = (const float4*)Ws + tx;
    const float* xr0 = &xs[(ty * 4 + 0) * G1_XSTRIDE];
    const float* xr1 = &xs[(ty * 4 + 1) * G1_XSTRIDE];
    const float* xr2 = &xs[(ty * 4 + 2) * G1_XSTRIDE];
    const float* xr3 = &xs[(ty * 4 + 3) * G1_XSTRIDE];

    #pragma unroll 8
    for (int k = 0; k < INCH; k++) {
        float4 w = WsRow[k * 16];
        float x0 = xr0[k], x1 = xr1[k], x2 = xr2[k], x3 = xr3[k];
        acc[0][0] = fmaf(x0, w.x, acc[0][0]); acc[0][1] = fmaf(x0, w.y, acc[0][1]);
        acc[0][2] = fmaf(x0, w.z, acc[0][2]); acc[0][3] = fmaf(x0, w.w, acc[0][3]);
        acc[1][0] = fmaf(x1, w.x, acc[1][0]); acc[1][1] = fmaf(x1, w.y, acc[1][1]);
        acc[1][2] = fmaf(x1, w.z, acc[1][2]); acc[1][3] = fmaf(x1, w.w, acc[1][3]);
        acc[2][0] = fmaf(x2, w.x, acc[2][0]); acc[2][1] = fmaf(x2, w.y, acc[2][1]);
        acc[2][2] = fmaf(x2, w.z, acc[2][2]); acc[2][3] = fmaf(x2, w.w, acc[2][3]);
        acc[3][0] = fmaf(x3, w.x, acc[3][0]); acc[3][1] = fmaf(x3, w.y, acc[3][1]);
        acc[3][2] = fmaf(x3, w.z, acc[3][2]); acc[3][3] = fmaf(x3, w.w, acc[3][3]);
    }

    #pragma unroll
    for (int i = 0; i < 4; i++) {
        int node = base + ty * 4 + i;
        if (node < NN)
            *(float4*)&g_h1[(size_t)node * C1 + tx * 4] =
                make_float4(acc[i][0], acc[i][1], acc[i][2], acc[i][3]);
    }

    float as0 = asrc[tx * 4 + 0], as1 = asrc[tx * 4 + 1], as2 = asrc[tx * 4 + 2], as3 = asrc[tx * 4 + 3];
    float ad0 = adst[tx * 4 + 0], ad1 = adst[tx * 4 + 1], ad2 = adst[tx * 4 + 2], ad3 = adst[tx * 4 + 3];
    __syncthreads();
    float* redS = xs;              // 128*17
    float* redD = xs + 128 * 17;   // 128*17
    #pragma unroll
    for (int i = 0; i < 4; i++) {
        int nl = ty * 4 + i;
        float ps = acc[i][0] * as0 + acc[i][1] * as1 + acc[i][2] * as2 + acc[i][3] * as3;
        float pd = acc[i][0] * ad0 + acc[i][1] * ad1 + acc[i][2] * ad2 + acc[i][3] * ad3;
        redS[nl * 17 + tx] = ps;
        redD[nl * 17 + tx] = pd;
    }
    __syncthreads();
    if (tid < 128) {
        int node = base + tid;
        if (node < NN) {
            float s = 0.f, d = 0.f;
            #pragma unroll
            for (int t = 0; t < 16; t++) { s += redS[tid * 17 + t]; d += redD[tid * 17 + t]; }
            g_ls[node] = s;
            g_ld[node] = d;
        }
    }
}

// ============================================================
// Layer2 projection + fused layer1 epilogue + fused zero of agg2/den.
// 64 nodes/block (grid 782), 256 threads, thread = 2 nodes x 4 channels.
// One division per NODE (not per element). ~26KB smem -> 8 blocks/SM.
// ============================================================
#define G2_XSTRIDE 68
__global__ __launch_bounds__(256) void gemm2_kernel(
    const float* __restrict__ b1, const float* __restrict__ W,
    const float* __restrict__ asrc, const float* __restrict__ adst)
{
    __shared__ float Ws[C1 * C2];           // 8KB
    __shared__ float xs[64 * G2_XSTRIDE];   // 17.4KB
    __shared__ float invs[64];
    __shared__ float b1s[C1];

    int tid = threadIdx.x;
    int tx = tid & 7;             // channels tx*4..+3
    int ty = tid >> 3;            // nodes ty*2, ty*2+1
    int base = blockIdx.x * 64;

    for (int i = tid; i < C1 * C2; i += 256) Ws[i] = W[i];
    if (tid < C1) b1s[tid] = b1[tid];

    // per-node inverse denominator, then zero den (only this block reads it)
    if (tid < 64) {
        int node = base + tid;
        float inv = 0.f;
        if (node < NN) {
            float den = g_den[node];
            inv = den > 0.f ? 1.f / den : 0.f;
            g_den[node] = 0.f;
        }
        invs[tid] = inv;
    }
    // zero agg2 rows for this block's nodes: 64 nodes * 8 float4 = 512 float4
    {
        float4 z4 = make_float4(0.f, 0.f, 0.f, 0.f);
        #pragma unroll
        for (int it = 0; it < 2; it++) {
            int f = it * 256 + tid;
            int n = base + (f >> 3);
            if (n < NN) *(float4*)&g_agg2[(size_t)n * C2 + (f & 7) * 4] = z4;
        }
    }
    __syncthreads();

    // stage x tile with epilogue: 64 nodes x 16 float4 = 1024 float4
    #pragma unroll
    for (int it = 0; it < 4; it++) {
        int f = it * 256 + tid;
        int n = f >> 4, k4 = f & 15;
        int node = base + n;
        float4 v = make_float4(0.f, 0.f, 0.f, 0.f);
        if (node < NN) {
            float inv = invs[n];
            float4 a = *(const float4*)&g_agg1[(size_t)node * C1 + k4 * 4];
            v.x = fmaxf(a.x * inv + b1s[k4 * 4 + 0], 0.f);
            v.y = fmaxf(a.y * inv + b1s[k4 * 4 + 1], 0.f);
            v.z = fmaxf(a.z * inv + b1s[k4 * 4 + 2], 0.f);
            v.w = fmaxf(a.w * inv + b1s[k4 * 4 + 3], 0.f);
        }
        *(float4*)&xs[n * G2_XSTRIDE + k4 * 4] = v;
    }
    __syncthreads();

    float acc[2][4];
    #pragma unroll
    for (int i = 0; i < 2; i++)
        #pragma unroll
        for (int j = 0; j < 4; j++) acc[i][j] = 0.f;

    const float4* WsRow = (const float4*)Ws + tx;
    const float* xr0 = &xs[(ty * 2 + 0) * G2_XSTRIDE];
    const float* xr1 = &xs[(ty * 2 + 1) * G2_XSTRIDE];

    #pragma unroll 8
    for (int k = 0; k < C1; k++) {
        float4 w = WsRow[k * 8];
        float x0 = xr0[k], x1 = xr1[k];
        acc[0][0] = fmaf(x0, w.x, acc[0][0]); acc[0][1] = fmaf(x0, w.y, acc[0][1]);
        acc[0][2] = fmaf(x0, w.z, acc[0][2]); acc[0][3] = fmaf(x0, w.w, acc[0][3]);
        acc[1][0] = fmaf(x1, w.x, acc[1][0]); acc[1][1] = fmaf(x1, w.y, acc[1][1]);
        acc[1][2] = fmaf(x1, w.z, acc[1][2]); acc[1][3] = fmaf(x1, w.w, acc[1][3]);
    }

    #pragma unroll
    for (int i = 0; i < 2; i++) {
        int node = base + ty * 2 + i;
        if (node < NN)
            *(float4*)&g_h2[(size_t)node * C2 + tx * 4] =
                make_float4(acc[i][0], acc[i][1], acc[i][2], acc[i][3]);
    }

    float as0 = asrc[tx * 4 + 0], as1 = asrc[tx * 4 + 1], as2 = asrc[tx * 4 + 2], as3 = asrc[tx * 4 + 3];
    float ad0 = adst[tx * 4 + 0], ad1 = adst[tx * 4 + 1], ad2 = adst[tx * 4 + 2], ad3 = adst[tx * 4 + 3];
    __syncthreads();
    float* redS = xs;             // 64*9
    float* redD = xs + 64 * 9;    // 64*9
    #pragma unroll
    for (int i = 0; i < 2; i++) {
        int nl = ty * 2 + i;
        float ps = acc[i][0] * as0 + acc[i][1] * as1 + acc[i][2] * as2 + acc[i][3] * as3;
        float pd = acc[i][0] * ad0 + acc[i][1] * ad1 + acc[i][2] * ad2 + acc[i][3] * ad3;
        redS[nl * 9 + tx] = ps;
        redD[nl * 9 + tx] = pd;
    }
    __syncthreads();
    if (tid < 64) {
        int node = base + tid;
        if (node < NN) {
            float s = 0.f, d = 0.f;
            #pragma unroll
            for (int t = 0; t < 8; t++) { s += redS[tid * 9 + t]; d += redD[tid * 9 + t]; }
            g_ls[node] = s;
            g_ld[node] = d;
        }
    }
}

// ============================================================
// Fused edge pass: logit -> exp -> denom atomic -> vector-red aggregate.
// ============================================================
template <int C>
__global__ void edge_fused(const int* __restrict__ src, const int* __restrict__ dst,
                           const float* __restrict__ h, float* __restrict__ agg)
{
    const int TPE = C / 4;
    int gi = blockIdx.x * blockDim.x + threadIdx.x;
    int e = gi / TPE;
    int lane = gi % TPE;
    if (e >= EE) return;
    int s = src[e], d = dst[e];
    float ev = 0.f;
    if (lane == 0) {
        float l = g_ls[s] + g_ld[d];
        l = l > 0.f ? l : SLOPE * l;
        ev = __expf(l);
        atomicAdd(&g_den[d], ev);
    }
    int leader = (threadIdx.x & 31) & ~(TPE - 1);
    ev = __shfl_sync(0xffffffffu, ev, leader);
    float4 hv = *reinterpret_cast<const float4*>(h + (size_t)s * C + lane * 4);
    float* p = agg + (size_t)d * C + lane * 4;
    asm volatile("red.global.add.v4.f32 [%0], {%1,%2,%3,%4};"
                 :: "l"(p), "f"(hv.x * ev), "f"(hv.y * ev), "f"(hv.z * ev), "f"(hv.w * ev)
                 : "memory");
}

// -------- final epilogue: out = agg2/den + b2 --------
__global__ void finalize_kernel(const float* __restrict__ b2, float* __restrict__ out)
{
    int i = blockIdx.x * blockDim.x + threadIdx.x;
    if (i >= NN * C2) return;
    int n = i >> 5, c = i & 31;
    float den = g_den[n];
    float inv = den > 0.f ? 1.f / den : 0.f;
    out[i] = g_agg2[i] * inv + b2[c];
}

extern "C" void kernel_launch(void* const* d_in, const int* in_sizes, int n_in,
                              void* d_out, int out_size)
{
    const float* x   = (const float*)d_in[0];
    const int*   ei  = (const int*)d_in[1];
    const float* W1  = (const float*)d_in[2];
    const float* as1 = (const float*)d_in[3];
    const float* ad1 = (const float*)d_in[4];
    const float* b1  = (const float*)d_in[5];
    const float* W2  = (const float*)d_in[6];
    const float* as2 = (const float*)d_in[7];
    const float* ad2 = (const float*)d_in[8];
    const float* b2  = (const float*)d_in[9];
    const int* src = ei;
    const int* dst = ei + EE;

    float *p_agg1, *p_agg2, *p_h1, *p_h2;
    cudaGetSymbolAddress((void**)&p_agg1, g_agg1);
    cudaGetSymbolAddress((void**)&p_agg2, g_agg2);
    cudaGetSymbolAddress((void**)&p_h1,   g_h1);
    cudaGetSymbolAddress((void**)&p_h2,   g_h2);

    static bool attr_set = false;
    if (!attr_set) {
        cudaFuncSetAttribute(gemm1_kernel, cudaFuncAttributeMaxDynamicSharedMemorySize, G1_SMEM);
        attr_set = true;
    }

    const int T = 256;

    // ---- layer 1 ----
    gemm1_kernel<<<(NN + 127) / 128, 512, G1_SMEM>>>(x, W1, as1, ad1);
    edge_fused<C1><<<EE * (C1 / 4) / T, T>>>(src, dst, p_h1, p_agg1);

    // ---- layer 2 ----
    gemm2_kernel<<<(NN + 63) / 64, T>>>(b1, W2, as2, ad2);
    edge_fused<C2><<<EE * (C2 / 4) / T, T>>>(src, dst, p_h2, p_agg2);

    finalize_kernel<<<(NN * C2 + T - 1) / T, T>>>(b2, (float*)d_out);
}